// round 2
// baseline (speedup 1.0000x reference)
#include <cuda_runtime.h>

#define T_    512
#define DF    64
#define NPAIR 60
#define NDIAG 1023
#define BIGV  1e10f

static __device__ float g_Dd[(size_t)NPAIR * NDIAG * T_];   // anti-diagonal layout cost matrices
static __device__ float g_raw[NPAIR];
static __device__ float g_Gp[64 * 48 * 48];                 // gram partials per k-chunk block

__device__ __forceinline__ float fex2(float x) { float y; asm("ex2.approx.f32 %0, %1;" : "=f"(y) : "f"(x)); return y; }
__device__ __forceinline__ float flg2(float x) { float y; asm("lg2.approx.f32 %0, %1;" : "=f"(y) : "f"(x)); return y; }

// ---------------------------------------------------------------------------
// Kernel A: pairwise squared-Euclidean cost tiles, written in anti-diagonal
// layout g_Dd[p][(i+j)][i] so the DP kernel reads coalesced.
// Grid: (8 j-tiles, 8 i-tiles, 60 pairs), 256 threads, 4x4 register tiles.
// ---------------------------------------------------------------------------
__global__ __launch_bounds__(256) void cost_kernel(const float* __restrict__ data,
                                                   const int* __restrict__ lens) {
    int p = blockIdx.z;
    int w = p / 15, jj = p % 15 + 1;
    int arow = w * 16, brow = arow + jj;
    int la = lens[arow], lb = lens[brow];
    int i0 = blockIdx.y * 64, j0 = blockIdx.x * 64;
    if (i0 >= la || j0 >= lb) return;   // cells never read by DP

    __shared__ float As[64][68];   // As[k][i], 16B-aligned rows
    __shared__ float Bs[64][68];
    __shared__ float Ct[64][66];   // pad 66 -> conflict-free diagonal reads
    __shared__ float a2s[64], b2s[64];

    int tid = threadIdx.x;
    const float* Ap = data + (size_t)arow * T_ * DF;
    const float* Bp = data + (size_t)brow * T_ * DF;
#pragma unroll
    for (int it = 0; it < 4; ++it) {
        int f = tid + it * 256;
        int r = f >> 4, q = f & 15;
        float4 va = *(const float4*)(Ap + (size_t)(i0 + r) * DF + q * 4);
        float4 vb = *(const float4*)(Bp + (size_t)(j0 + r) * DF + q * 4);
        As[q * 4 + 0][r] = va.x; As[q * 4 + 1][r] = va.y; As[q * 4 + 2][r] = va.z; As[q * 4 + 3][r] = va.w;
        Bs[q * 4 + 0][r] = vb.x; Bs[q * 4 + 1][r] = vb.y; Bs[q * 4 + 2][r] = vb.z; Bs[q * 4 + 3][r] = vb.w;
    }
    __syncthreads();

    if (tid < 64) {
        float s = 0.f;
#pragma unroll
        for (int k = 0; k < 64; ++k) { float v = As[k][tid]; s = fmaf(v, v, s); }
        a2s[tid] = s;
    } else if (tid < 128) {
        int r = tid - 64; float s = 0.f;
#pragma unroll
        for (int k = 0; k < 64; ++k) { float v = Bs[k][r]; s = fmaf(v, v, s); }
        b2s[r] = s;
    }

    int tx = tid & 15, ty = tid >> 4;
    int ib = ty * 4, jb = tx * 4;
    float acc[4][4] = {};
#pragma unroll 16
    for (int k = 0; k < 64; ++k) {
        float4 av = *(const float4*)&As[k][ib];
        float4 bv = *(const float4*)&Bs[k][jb];
        acc[0][0] = fmaf(av.x, bv.x, acc[0][0]); acc[0][1] = fmaf(av.x, bv.y, acc[0][1]);
        acc[0][2] = fmaf(av.x, bv.z, acc[0][2]); acc[0][3] = fmaf(av.x, bv.w, acc[0][3]);
        acc[1][0] = fmaf(av.y, bv.x, acc[1][0]); acc[1][1] = fmaf(av.y, bv.y, acc[1][1]);
        acc[1][2] = fmaf(av.y, bv.z, acc[1][2]); acc[1][3] = fmaf(av.y, bv.w, acc[1][3]);
        acc[2][0] = fmaf(av.z, bv.x, acc[2][0]); acc[2][1] = fmaf(av.z, bv.y, acc[2][1]);
        acc[2][2] = fmaf(av.z, bv.z, acc[2][2]); acc[2][3] = fmaf(av.z, bv.w, acc[2][3]);
        acc[3][0] = fmaf(av.w, bv.x, acc[3][0]); acc[3][1] = fmaf(av.w, bv.y, acc[3][1]);
        acc[3][2] = fmaf(av.w, bv.z, acc[3][2]); acc[3][3] = fmaf(av.w, bv.w, acc[3][3]);
    }
    __syncthreads();   // also guarantees a2s/b2s visible
#pragma unroll
    for (int r = 0; r < 4; ++r)
#pragma unroll
        for (int c = 0; c < 4; ++c)
            Ct[ib + r][jb + c] = a2s[ib + r] + b2s[jb + c] - 2.f * acc[r][c];
    __syncthreads();

    // anti-diagonal write-out (coalesced in i)
    float* Dp = g_Dd + (size_t)p * NDIAG * T_;
    int kdo = tid >> 6, t = tid & 63;
    for (int kd0 = 0; kd0 < 127; kd0 += 4) {
        int kd = kd0 + kdo;
        if (kd < 127) {
            int ilo = kd > 63 ? kd - 63 : 0;
            int ihi = kd < 63 ? kd : 63;
            int ci = ilo + t;
            if (ci <= ihi) {
                int cj = kd - ci;
                Dp[(size_t)(i0 + ci + j0 + cj) * T_ + (i0 + ci)] = Ct[ci][cj];
            }
        }
    }
}

// ---------------------------------------------------------------------------
// Kernel B: soft-DTW anti-diagonal wavefront. One CTA per pair, thread i owns
// row i. 3 rolling diagonals in smem, 2-deep cost prefetch, 1 bar per step.
// ---------------------------------------------------------------------------
__global__ __launch_bounds__(512) void dtw_kernel(const int* __restrict__ lens) {
    int p = blockIdx.x;
    int w = p / 15, jj = p % 15 + 1;
    int la = lens[w * 16], lb = lens[w * 16 + jj];

    __shared__ float buf[3][520];
    int tid = threadIdx.x;
    int i = tid + 1;                    // DP row index (1..512)
    for (int q = tid; q < 3 * 520; q += 512) ((float*)buf)[q] = BIGV;
    __syncthreads();
    if (tid == 0) buf[0][0] = 0.f;      // R[0,0] = 0
    __syncthreads();

    const float* Dp = g_Dd + (size_t)p * NDIAG * T_;
    int kmax = la + lb;
    const float c1 = 0.28853900817779268f;   // 1/(GAMMA*ln2)
    const float gln2 = 3.4657359027997265f;  // GAMMA*ln2

    auto loadc = [&](int k) -> float {
        if (k <= kmax && i <= la && i <= k - 1 && (k - i) <= lb)
            return Dp[(size_t)(k - 2) * T_ + (i - 1)];
        return 0.f;
    };
    float cs0 = loadc(2), cs1 = loadc(3);

    float* p2 = buf[0];
    float* p1 = buf[1];
    float* cur = buf[2];
    for (int k = 2; k <= kmax; ++k) {
        float cs2 = loadc(k + 2);      // prefetch 2 ahead
        bool act = (i <= la) && (i <= k - 1) && (k - i) <= lb;
        if (act) {
            float x1 = p2[i - 1], x2 = p1[i - 1], x3 = p1[i];
            float m = fminf(x1, fminf(x2, x3));
            float S = fex2((m - x1) * c1) + fex2((m - x2) * c1) + fex2((m - x3) * c1);
            float s = cs0 + m - gln2 * flg2(S);
            cur[i] = s;
            if (k == kmax && i == la) g_raw[p] = s;
        }
        if (tid == 0) cur[0] = BIGV;   // R[0,k] boundary
        __syncthreads();
        cs0 = cs1; cs1 = cs2;
        float* tmp = p2; p2 = p1; p1 = cur; cur = tmp;
    }
}

// ---------------------------------------------------------------------------
// Kernel C: 44x44 gram over flattened rows (K = 32768), k-split into 64
// blocks, deterministic per-block partials in g_Gp.
// ---------------------------------------------------------------------------
__global__ __launch_bounds__(256) void gram_kernel(const float* __restrict__ data) {
    __shared__ float St[64][49];
    int tid = threadIdx.x;
    int tx = tid & 15, ty = tid >> 4;
    float acc[3][3] = {};
    int k0 = blockIdx.x * 512;
    for (int sub = 0; sub < 8; ++sub) {
        int kb = k0 + sub * 64;
        __syncthreads();
#pragma unroll
        for (int it = 0; it < 3; ++it) {
            int f = tid + it * 256;
            if (f < 44 * 16) {
                int r = f >> 4, q = f & 15;
                int n = (r / 11) * 16 + (r % 11);
                float4 v = *(const float4*)(data + (size_t)n * 32768 + kb + q * 4);
                St[q * 4 + 0][r] = v.x; St[q * 4 + 1][r] = v.y;
                St[q * 4 + 2][r] = v.z; St[q * 4 + 3][r] = v.w;
            }
        }
        { int kk = tid >> 2; int r = 44 + (tid & 3); St[kk][r] = 0.f; }
        __syncthreads();
#pragma unroll 8
        for (int kk = 0; kk < 64; ++kk) {
            float a0 = St[kk][ty * 3 + 0], a1 = St[kk][ty * 3 + 1], a2 = St[kk][ty * 3 + 2];
            float b0 = St[kk][tx * 3 + 0], b1 = St[kk][tx * 3 + 1], b2 = St[kk][tx * 3 + 2];
            acc[0][0] = fmaf(a0, b0, acc[0][0]); acc[0][1] = fmaf(a0, b1, acc[0][1]); acc[0][2] = fmaf(a0, b2, acc[0][2]);
            acc[1][0] = fmaf(a1, b0, acc[1][0]); acc[1][1] = fmaf(a1, b1, acc[1][1]); acc[1][2] = fmaf(a1, b2, acc[1][2]);
            acc[2][0] = fmaf(a2, b0, acc[2][0]); acc[2][1] = fmaf(a2, b1, acc[2][1]); acc[2][2] = fmaf(a2, b2, acc[2][2]);
        }
    }
    float* gp = g_Gp + blockIdx.x * 2304;
#pragma unroll
    for (int r = 0; r < 3; ++r)
#pragma unroll
        for (int c = 0; c < 3; ++c)
            gp[(ty * 3 + r) * 48 + (tx * 3 + c)] = acc[r][c];
}

// ---------------------------------------------------------------------------
// Kernel D: deterministic finishing — triplet loss, 9 MMDs, output scalar.
// ---------------------------------------------------------------------------
__global__ __launch_bounds__(512) void final_kernel(const int* __restrict__ lens,
                                                    float* __restrict__ out) {
    __shared__ float sG[44 * 44];
    __shared__ float L2s[484];
    __shared__ float dist[60];
    __shared__ float sTotal, sBw, mmax;
    int tid = threadIdx.x;

    // reduce gram partials (fixed order -> deterministic)
    for (int t = tid; t < 44 * 44; t += 512) {
        int a = t / 44, b = t % 44;
        float s = 0.f;
        for (int blk = 0; blk < 64; ++blk) s += g_Gp[blk * 2304 + a * 48 + b];
        sG[t] = s;
    }
    if (tid < 60) {
        int w = tid / 15, jj = tid % 15 + 1;
        dist[tid] = g_raw[tid] / (float)(lens[w * 16] + lens[w * 16 + jj]);
    }
    __syncthreads();

    if (tid == 0) {
        float total = 0.f;
        for (int w = 0; w < 4; ++w) {
            const float* dw = dist + w * 15;
            float mg = 0.f;
            for (int g = 0; g < 5; ++g) mg += dw[g];
            mg *= 0.2f;
            float dk = sqrtf(fabsf(mg));
            float dg[5], dn[10];
            for (int g = 0; g < 5; ++g) dg[g] = dw[g] / dk;
            for (int s = 0; s < 10; ++s) dn[s] = dw[5 + s] / dk;
            float sum = 0.f; int cnt = 0;
            for (int g = 0; g < 5; ++g)
                for (int s = 0; s < 10; ++s) {
                    float v = dg[g] + 1.0f - dn[s];
                    if (v > 0.f) { sum += v; cnt++; }
                }
            float ca = 0.f, cb = 0.f;
            for (int g = 0; g < 5; ++g) ca += dg[g];
            ca *= 0.2f;
            for (int s = 0; s < 5; ++s) cb += dn[s];
            cb *= 0.2f;
            float intra = 0.f;
            for (int g = 0; g < 5; ++g) intra += dg[g] - ca;
            float inter = fmaxf(0.f, 1.0f - fabsf(ca - cb));
            float lv = sum / ((float)cnt + 1.f);
            total += lv + intra * 0.1f + inter * 0.1f;
        }
        sTotal = total * 0.25f;
        mmax = 0.f;
    }
    __syncthreads();

    const int pwi[9] = {0, 0, 0, 1, 1, 2, 2, 3, 3};
    const int pwj[9] = {1, 2, 3, 2, 3, 1, 3, 1, 2};
    for (int pp = 0; pp < 9; ++pp) {
        int a = tid / 22, b = tid % 22;
        if (tid < 484) {
            int ra = (a < 11) ? pwi[pp] * 11 + a : pwj[pp] * 11 + (a - 11);
            int rb = (b < 11) ? pwi[pp] * 11 + b : pwj[pp] * 11 + (b - 11);
            L2s[tid] = sG[ra * 44 + ra] + sG[rb * 44 + rb] - 2.f * sG[ra * 44 + rb];
        }
        __syncthreads();
        if (tid == 0) {
            float s = 0.f;
            for (int t = 0; t < 484; ++t) s += L2s[t];
            sBw = s / 462.f * 0.25f;   // /(m^2-m), then / K_MUL^(K_NUM//2)=4
        }
        __syncthreads();
        if (tid < 484) {
            float l2 = L2s[tid];
            float bwa = sBw;
            float kk = 0.f;
            for (int q = 0; q < 5; ++q) { kk += expf(-l2 / bwa); bwa *= 2.f; }
            L2s[tid] = kk;
        }
        __syncthreads();
        if (tid == 0) {
            float q00 = 0, q01 = 0, q10 = 0, q11 = 0;
            for (int t = 0; t < 484; ++t) {
                int aa = t / 22, bb = t % 22;
                float v = L2s[t];
                if (aa < 11) { if (bb < 11) q00 += v; else q01 += v; }
                else         { if (bb < 11) q10 += v; else q11 += v; }
            }
            float mmd = (q00 + q11 - q01 - q10) / 121.f;
            mmax = fmaxf(mmax, mmd);   // zero-padded max -> clamp at 0
        }
        __syncthreads();
    }
    if (tid == 0) out[0] = sTotal + mmax * 0.1f;
}

// ---------------------------------------------------------------------------
extern "C" void kernel_launch(void* const* d_in, const int* in_sizes, int n_in,
                              void* d_out, int out_size) {
    const float* data = (const float*)d_in[0];
    const int* lens = (const int*)d_in[1];
    float* out = (float*)d_out;

    dim3 gA(8, 8, NPAIR);
    cost_kernel<<<gA, 256>>>(data, lens);
    dtw_kernel<<<NPAIR, 512>>>(lens);
    gram_kernel<<<64, 256>>>(data);
    final_kernel<<<1, 512>>>(lens, out);
}